// round 14
// baseline (speedup 1.0000x reference)
#include <cuda_runtime.h>
#include <cuda_fp16.h>
#include <math.h>
#include <stdint.h>

#define BSZ 8
#define TQ  1024
#define SK  1500
#define DM  1024
#define NH  16
#define DH  64
#define SCALE 0.125f
#define LOG2E 1.4426950408889634f

// fp16 scratch (static device allocations)
__device__ __half g_xh[BSZ * TQ * DM];
__device__ __half g_wqh[DM * DM];
__device__ __half g_woh[DM * DM];
__device__ __half g_kh[BSZ * SK * DM];
__device__ __half g_vh[BSZ * SK * DM];
__device__ __half g_qh[BSZ * TQ * DM];
__device__ __half g_ah[BSZ * TQ * DM];

// ---------------------------------------------------------------------------
__device__ __forceinline__ unsigned pack2h(float lo, float hi) {
    unsigned u;
    asm("cvt.rn.f16x2.f32 %0, %1, %2;" : "=r"(u) : "f"(hi), "f"(lo));
    return u;
}
__device__ __forceinline__ unsigned ex2h2(unsigned a) {
    unsigned d;
    asm("ex2.approx.f16x2 %0, %1;" : "=r"(d) : "r"(a));
    return d;
}
__device__ __forceinline__ uint2 cvt4(float4 v) {
    uint2 u;
    u.x = pack2h(v.x, v.y);
    u.y = pack2h(v.z, v.w);
    return u;
}
__device__ __forceinline__ void mma_f16(float c[4], const unsigned a[4],
                                        unsigned b0, unsigned b1) {
    asm volatile(
        "mma.sync.aligned.m16n8k16.row.col.f32.f16.f16.f32 "
        "{%0,%1,%2,%3}, {%4,%5,%6,%7}, {%8,%9}, {%0,%1,%2,%3};"
        : "+f"(c[0]), "+f"(c[1]), "+f"(c[2]), "+f"(c[3])
        : "r"(a[0]), "r"(a[1]), "r"(a[2]), "r"(a[3]), "r"(b0), "r"(b1));
}
__device__ __forceinline__ void ldsm4(unsigned &r0, unsigned &r1, unsigned &r2,
                                      unsigned &r3, unsigned addr) {
    asm volatile("ldmatrix.sync.aligned.m8n8.x4.shared.b16 {%0,%1,%2,%3}, [%4];"
                 : "=r"(r0), "=r"(r1), "=r"(r2), "=r"(r3) : "r"(addr));
}
__device__ __forceinline__ void ldsm4t(unsigned &r0, unsigned &r1, unsigned &r2,
                                       unsigned &r3, unsigned addr) {
    asm volatile("ldmatrix.sync.aligned.m8n8.x4.trans.shared.b16 {%0,%1,%2,%3}, [%4];"
                 : "=r"(r0), "=r"(r1), "=r"(r2), "=r"(r3) : "r"(addr));
}
__device__ __forceinline__ void cp16(unsigned d, const void* s) {
    asm volatile("cp.async.cg.shared.global [%0], [%1], 16;" :: "r"(d), "l"(s));
}
__device__ __forceinline__ void cp16z(unsigned d, const void* s, int ssz) {
    asm volatile("cp.async.cg.shared.global [%0], [%1], 16, %2;"
                 :: "r"(d), "l"(s), "r"(ssz));
}
__device__ __forceinline__ void cp_commit() {
    asm volatile("cp.async.commit_group;");
}
template <int N>
__device__ __forceinline__ void cp_wait() {
    asm volatile("cp.async.wait_group %0;" :: "n"(N));
}
__device__ __forceinline__ void store2(float* C, size_t idx, float v0, float v1) {
    *(float2*)&C[idx] = make_float2(v0, v1);
}
__device__ __forceinline__ void store2(__half* C, size_t idx, float v0, float v1) {
    *(unsigned*)&C[idx] = pack2h(v0, v1);
}

// ---------------------------------------------------------------------------
// Single merged fp32 -> fp16 convert for all 5 tensors (uint4 stores).
// Indices in 4-elem units; each thread converts 2 consecutive (16B store).
// ---------------------------------------------------------------------------
#define CVT_N4 8765440
__global__ void cvt_all(const float4* __restrict__ x,  const float4* __restrict__ wq,
                        const float4* __restrict__ wo, const float4* __restrict__ k,
                        const float4* __restrict__ v,
                        uint2* xh, uint2* wqh, uint2* woh, uint2* kh, uint2* vh)
{
    int i = (blockIdx.x * blockDim.x + threadIdx.x) * 2;
    const float4* s; uint2* d; int o;
    if (i < 2097152)      { s = x;  d = xh;  o = i; }
    else if (i < 2359296) { s = wq; d = wqh; o = i - 2097152; }
    else if (i < 2621440) { s = wo; d = woh; o = i - 2359296; }
    else if (i < 5693440) { s = k;  d = kh;  o = i - 2621440; }
    else if (i < 8765440) { s = v;  d = vh;  o = i - 5693440; }
    else return;
    uint2 a = cvt4(s[o]);
    uint2 b = cvt4(s[o + 1]);
    uint4 w; w.x = a.x; w.y = a.y; w.z = b.x; w.w = b.y;
    *(uint4*)&d[o] = w;
}

// ---------------------------------------------------------------------------
// C[m,n] = (sum_k A[m,k]*W[n,k] + bias[n]) * alpha — fp16 m16n8k16, cp.async.
// 128x128 tile, BK=32, 3-stage pipeline, 4 warps, warp tile 64x64.
// 32 independent accumulator chains per warp; MMA:LDSM = 4.
// ---------------------------------------------------------------------------
#define ASTR   40
#define G_HALF (128 * ASTR)
#define G_STGB (2 * G_HALF * 2)
#define G_SMEM (3 * G_STGB)

template <typename OutT>
__global__ __launch_bounds__(128, 2)
void gemm_h(const __half* __restrict__ A, const __half* __restrict__ W,
            const float* __restrict__ bias, OutT* __restrict__ C,
            int M, int N, int K, float alpha)
{
    extern __shared__ __align__(16) char dynsm[];
    const unsigned base = (unsigned)__cvta_generic_to_shared(dynsm);

    const int tid  = threadIdx.x;
    const int lane = tid & 31;
    const int wid  = tid >> 5;
    const int g    = lane >> 2;
    const int t    = lane & 3;
    const int wm   = (wid & 1) * 64;
    const int wn   = (wid >> 1) * 64;
    const int m0   = blockIdx.y * 128;
    const int n0   = blockIdx.x * 128;

    // loader: thread = one row of A and one row of W, 4x16B chunks each
    const __half* Ap = A + (size_t)(m0 + tid) * K;
    const __half* Wp = W + (size_t)(n0 + tid) * K;
    const unsigned sOff = (unsigned)(tid * ASTR * 2);

    auto cpstage = [&](int stage) {
        int k0 = stage * 32;
        unsigned sb = base + (unsigned)(stage % 3) * G_STGB;
        unsigned ab = sb + sOff;
        unsigned wb = sb + G_HALF * 2 + sOff;
#pragma unroll
        for (int c = 0; c < 4; c++) {
            cp16(ab + c * 16, Ap + k0 + c * 8);
            cp16(wb + c * 16, Wp + k0 + c * 8);
        }
        cp_commit();
    };

    const int ro = lane & 7;
    const int ti = lane >> 3;
    const unsigned aLane = (unsigned)(((wm + (ti & 1) * 8 + ro) * ASTR + (ti >> 1) * 8) * 2);
    const unsigned bLane = (unsigned)(((wn + (ti >> 1) * 8 + ro) * ASTR + (ti & 1) * 8) * 2);

    float acc[4][8][4];
#pragma unroll
    for (int i = 0; i < 4; i++)
#pragma unroll
        for (int j = 0; j < 8; j++)
#pragma unroll
            for (int e = 0; e < 4; e++) acc[i][j][e] = 0.f;

    const int NITER = K / 32;
    cpstage(0);
    cpstage(1);

    for (int i = 0; i < NITER; i++) {
        if (i + 1 < NITER) cp_wait<1>(); else cp_wait<0>();
        __syncthreads();
        if (i + 2 < NITER) cpstage(i + 2);

        const unsigned sb = base + (unsigned)(i % 3) * G_STGB;
        const unsigned aB = sb;
        const unsigned wB = sb + G_HALF * 2;
#pragma unroll
        for (int ks = 0; ks < 2; ks++) {
            unsigned af[4][4], bf[8][2];
#pragma unroll
            for (int mi = 0; mi < 4; mi++)
                ldsm4(af[mi][0], af[mi][1], af[mi][2], af[mi][3],
                      aB + aLane + (unsigned)((mi * 16 * ASTR + ks * 16) * 2));
#pragma unroll
            for (int np = 0; np < 4; np++)
                ldsm4(bf[2 * np][0], bf[2 * np][1], bf[2 * np + 1][0], bf[2 * np + 1][1],
                      wB + bLane + (unsigned)((np * 16 * ASTR + ks * 16) * 2));
#pragma unroll
            for (int mi = 0; mi < 4; mi++)
#pragma unroll
                for (int ni = 0; ni < 8; ni++)
                    mma_f16(acc[mi][ni], af[mi], bf[ni][0], bf[ni][1]);
        }
    }

#pragma unroll
    for (int mi = 0; mi < 4; mi++) {
#pragma unroll
        for (int ni = 0; ni < 8; ni++) {
            int mA = m0 + wm + mi * 16 + g;
            int nA = n0 + wn + ni * 8 + 2 * t;
            float b0 = bias[nA], b1 = bias[nA + 1];
            store2(C, (size_t)mA * N + nA,
                   (acc[mi][ni][0] + b0) * alpha, (acc[mi][ni][1] + b1) * alpha);
            store2(C, (size_t)(mA + 8) * N + nA,
                   (acc[mi][ni][2] + b0) * alpha, (acc[mi][ni][3] + b1) * alpha);
        }
    }
}

// ---------------------------------------------------------------------------
// Flash attention (unchanged from R13): fp16 mma, 3-stage cp.async, lazy
// softmax (frozen chunk-0 reference), l via ones-column MMA.
// ---------------------------------------------------------------------------
#define CH     64
#define KSTR   72
#define NCH    ((SK + CH - 1) / CH)
#define A_HALF (CH * KSTR)
#define A_STGB (2 * A_HALF * 2)
#define A_SMEM (3 * A_STGB)

__global__ __launch_bounds__(256, 2)
void attn_h(const __half* __restrict__ Kin, const __half* __restrict__ Vin,
            __half* __restrict__ Out)
{
    extern __shared__ __align__(16) char dynsm[];
    const unsigned base = (unsigned)__cvta_generic_to_shared(dynsm);

    const int tid  = threadIdx.x;
    const int lane = tid & 31;
    const int wid  = tid >> 5;
    const int g    = lane >> 2;
    const int t    = lane & 3;
    const int b    = blockIdx.z;
    const int h    = blockIdx.y;

    const int key = tid >> 2;
    const int d0  = (tid & 3) * 16;

    const __half* Kb = Kin + (size_t)b * SK * DM + h * DH;
    const __half* Vb = Vin + (size_t)b * SK * DM + h * DH;
    const unsigned sOff = (unsigned)((key * KSTR + d0) * 2);

    auto cpstage = [&](int ci) {
        int s = ci * CH + key;
        int ssz = (s < SK) ? 16 : 0;
        size_t go = (size_t)(s < SK ? s : 0) * DM + d0;
        unsigned sb = base + (unsigned)(ci % 3) * A_STGB;
        unsigned kb = sb + sOff;
        unsigned vb = sb + A_HALF * 2 + sOff;
        cp16z(kb,      Kb + go,     ssz);
        cp16z(kb + 16, Kb + go + 8, ssz);
        cp16z(vb,      Vb + go,     ssz);
        cp16z(vb + 16, Vb + go + 8, ssz);
        cp_commit();
    };

    // Q fragments (fp16, pre-scaled by SCALE)
    const int rb = b * TQ + blockIdx.x * 128 + wid * 16;
    unsigned qf[4][4];
#pragma unroll
    for (int kt = 0; kt < 4; kt++) {
        int col = h * DH + kt * 16 + 2 * t;
        qf[kt][0] = *(const unsigned*)&g_qh[(size_t)(rb + g)     * DM + col];
        qf[kt][1] = *(const unsigned*)&g_qh[(size_t)(rb + g + 8) * DM + col];
        qf[kt][2] = *(const unsigned*)&g_qh[(size_t)(rb + g)     * DM + col + 8];
        qf[kt][3] = *(const unsigned*)&g_qh[(size_t)(rb + g + 8) * DM + col + 8];
    }

    const int ro = lane & 7;
    const int ti = lane >> 3;
    const unsigned kLane = (unsigned)((((ti >> 1) * 8 + ro) * KSTR + (ti & 1) * 8) * 2);
    const unsigned vLane = (unsigned)((((ti & 1) * 8 + ro) * KSTR + (ti >> 1) * 8) * 2);

    float nb0 = 0.f, nb1 = 0.f;
    float lacc[4] = {0.f, 0.f, 0.f, 0.f};
    float o[8][4];
#pragma unroll
    for (int nt = 0; nt < 8; nt++)
#pragma unroll
        for (int e = 0; e < 4; e++) o[nt][e] = 0.f;

    const unsigned ones2 = 0x3C003C00u;

    cpstage(0);
    cpstage(1);

    for (int i = 0; i < NCH; i++) {
        if (i + 1 < NCH) cp_wait<1>(); else cp_wait<0>();
        __syncthreads();
        if (i + 2 < NCH) cpstage(i + 2);

        const unsigned sb = base + (unsigned)(i % 3) * A_STGB;

        // ---- S = Q · K^T ----
        float sacc[8][4];
#pragma unroll
        for (int nt = 0; nt < 8; nt++)
#pragma unroll
            for (int e = 0; e < 4; e++) sacc[nt][e] = 0.f;

        const unsigned kB = sb + kLane;
#pragma unroll
        for (int kt = 0; kt < 4; kt++) {
#pragma unroll
            for (int np = 0; np < 4; np++) {
                unsigned b0e, b1e, b0o, b1o;
                ldsm4(b0e, b1e, b0o, b1o,
                      kB + (unsigned)((np * 16 * KSTR + kt * 16) * 2));
                mma_f16(sacc[2 * np],     qf[kt], b0e, b1e);
                mma_f16(sacc[2 * np + 1], qf[kt], b0o, b1o);
            }
        }

        // ---- tail mask ----
        const int s0c = i * CH;
        if (s0c + CH > SK) {
#pragma unroll
            for (int nt = 0; nt < 8; nt++) {
                int c = s0c + nt * 8 + 2 * t;
                if (c >= SK)     { sacc[nt][0] = -INFINITY; sacc[nt][2] = -INFINITY; }
                if (c + 1 >= SK) { sacc[nt][1] = -INFINITY; sacc[nt][3] = -INFINITY; }
            }
        }

        // ---- chunk 0: freeze softmax reference ----
        if (i == 0) {
            float mx0 = -INFINITY, mx1 = -INFINITY;
#pragma unroll
            for (int nt = 0; nt < 8; nt++) {
                mx0 = fmaxf(mx0, fmaxf(sacc[nt][0], sacc[nt][1]));
                mx1 = fmaxf(mx1, fmaxf(sacc[nt][2], sacc[nt][3]));
            }
            mx0 = fmaxf(mx0, __shfl_xor_sync(0xffffffffu, mx0, 1));
            mx0 = fmaxf(mx0, __shfl_xor_sync(0xffffffffu, mx0, 2));
            mx1 = fmaxf(mx1, __shfl_xor_sync(0xffffffffu, mx1, 1));
            mx1 = fmaxf(mx1, __shfl_xor_sync(0xffffffffu, mx1, 2));
            nb0 = -mx0 * LOG2E;
            nb1 = -mx1 * LOG2E;
        }

        // ---- P = ex2(s*log2e + nb) in fp16x2 ----
        unsigned punt[8][2];
#pragma unroll
        for (int nt = 0; nt < 8; nt++) {
            float a0 = fmaf(sacc[nt][0], LOG2E, nb0);
            float a1 = fmaf(sacc[nt][1], LOG2E, nb0);
            float a2 = fmaf(sacc[nt][2], LOG2E, nb1);
            float a3 = fmaf(sacc[nt][3], LOG2E, nb1);
            punt[nt][0] = ex2h2(pack2h(a0, a1));
            punt[nt][1] = ex2h2(pack2h(a2, a3));
        }

        // ---- O += P · V ; l += P · 1 ----
        const unsigned vB = sb + A_HALF * 2 + vLane;
#pragma unroll
        for (int kt2 = 0; kt2 < 4; kt2++) {
            unsigned pa[4];
            pa[0] = punt[2 * kt2][0];
            pa[1] = punt[2 * kt2][1];
            pa[2] = punt[2 * kt2 + 1][0];
            pa[3] = punt[2 * kt2 + 1][1];
            mma_f16(lacc, pa, ones2, ones2);
#pragma unroll
            for (int np = 0; np < 4; np++) {
                unsigned b0e, b1e, b0o, b1o;
                ldsm4t(b0e, b1e, b0o, b1o,
                       vB + (unsigned)((kt2 * 16 * KSTR + np * 16) * 2));
                mma_f16(o[2 * np],     pa, b0e, b1e);
                mma_f16(o[2 * np + 1], pa, b0o, b1o);
            }
        }
    }

    float inv0 = 1.f / lacc[0];
    float inv1 = 1.f / lacc[2];

#pragma unroll
    for (int nt = 0; nt < 8; nt++) {
        int col = h * DH + nt * 8 + 2 * t;
        *(unsigned*)&Out[(size_t)(rb + g) * DM + col] =
            pack2h(o[nt][0] * inv0, o[nt][1] * inv0);
        *(unsigned*)&Out[(size_t)(rb + g + 8) * DM + col] =
            pack2h(o[nt][2] * inv1, o[nt][3] * inv1);
    }
}

// ---------------------------------------------------------------------------
extern "C" void kernel_launch(void* const* d_in, const int* in_sizes, int n_in,
                              void* d_out, int out_size)
{
    const float* x  = (const float*)d_in[0];
    const float* k  = (const float*)d_in[1];
    const float* v  = (const float*)d_in[2];
    const float* wq = (const float*)d_in[3];
    const float* bq = (const float*)d_in[4];
    const float* wo = (const float*)d_in[5];
    const float* bo = (const float*)d_in[6];
    float* out = (float*)d_out;

    void *p_xh, *p_wqh, *p_woh, *p_kh, *p_vh, *p_qh, *p_ah;
    cudaGetSymbolAddress(&p_xh, g_xh);
    cudaGetSymbolAddress(&p_wqh, g_wqh);
    cudaGetSymbolAddress(&p_woh, g_woh);
    cudaGetSymbolAddress(&p_kh, g_kh);
    cudaGetSymbolAddress(&p_vh, g_vh);
    cudaGetSymbolAddress(&p_qh, g_qh);
    cudaGetSymbolAddress(&p_ah, g_ah);
    __half* xh  = (__half*)p_xh;
    __half* wqh = (__half*)p_wqh;
    __half* woh = (__half*)p_woh;
    __half* kh  = (__half*)p_kh;
    __half* vh  = (__half*)p_vh;
    __half* qh  = (__half*)p_qh;
    __half* ah  = (__half*)p_ah;

    static int attr_done = 0;
    if (!attr_done) {
        cudaFuncSetAttribute(gemm_h<__half>,
                             cudaFuncAttributeMaxDynamicSharedMemorySize, G_SMEM);
        cudaFuncSetAttribute(gemm_h<float>,
                             cudaFuncAttributeMaxDynamicSharedMemorySize, G_SMEM);
        cudaFuncSetAttribute(attn_h,
                             cudaFuncAttributeMaxDynamicSharedMemorySize, A_SMEM);
        attr_done = 1;
    }

    const int M = BSZ * TQ, N = DM, K = DM;

    // 0) all fp32 -> fp16 converts in one launch
    {
        int nthread = CVT_N4 / 2;
        cvt_all<<<(nthread + 255) / 256, 256>>>(
            (const float4*)x, (const float4*)wq, (const float4*)wo,
            (const float4*)k, (const float4*)v,
            (uint2*)xh, (uint2*)wqh, (uint2*)woh, (uint2*)kh, (uint2*)vh);
    }
    // 1) Q projection (+bias, *SCALE) -> fp16
    {
        dim3 grid(N / 128, M / 128);
        gemm_h<__half><<<grid, 128, G_SMEM>>>(xh, wqh, bq, qh, M, N, K, SCALE);
    }
    // 2) Attention -> fp16
    {
        dim3 grid(TQ / 128, NH, BSZ);
        attn_h<<<grid, 256, A_SMEM>>>(kh, vh, ah);
    }
    // 3) Output projection (+bias) -> fp32
    {
        dim3 grid(N / 128, M / 128);
        gemm_h<float><<<grid, 128, G_SMEM>>>(ah, woh, bo, out, M, N, K, 1.0f);
    }
}

// round 17
// speedup vs baseline: 1.0404x; 1.0404x over previous
#include <cuda_runtime.h>
#include <cuda_fp16.h>
#include <math.h>
#include <stdint.h>

#define BSZ 8
#define TQ  1024
#define SK  1500
#define DM  1024
#define NH  16
#define DH  64
#define SCALE 0.125f
#define LOG2E 1.4426950408889634f

// fp16 scratch (static device allocations)
__device__ __half g_xh[BSZ * TQ * DM];
__device__ __half g_wqh[DM * DM];
__device__ __half g_woh[DM * DM];
__device__ __half g_kh[BSZ * SK * DM];
__device__ __half g_vh[BSZ * SK * DM];
__device__ __half g_qh[BSZ * TQ * DM];
__device__ __half g_ah[BSZ * TQ * DM];

// ---------------------------------------------------------------------------
__device__ __forceinline__ unsigned pack2h(float lo, float hi) {
    unsigned u;
    asm("cvt.rn.f16x2.f32 %0, %1, %2;" : "=r"(u) : "f"(hi), "f"(lo));
    return u;
}
__device__ __forceinline__ unsigned ex2h2(unsigned a) {
    unsigned d;
    asm("ex2.approx.f16x2 %0, %1;" : "=r"(d) : "r"(a));
    return d;
}
__device__ __forceinline__ uint2 cvt4(float4 v) {
    uint2 u;
    u.x = pack2h(v.x, v.y);
    u.y = pack2h(v.z, v.w);
    return u;
}
__device__ __forceinline__ void mma_f16(float c[4], const unsigned a[4],
                                        unsigned b0, unsigned b1) {
    asm volatile(
        "mma.sync.aligned.m16n8k16.row.col.f32.f16.f16.f32 "
        "{%0,%1,%2,%3}, {%4,%5,%6,%7}, {%8,%9}, {%0,%1,%2,%3};"
        : "+f"(c[0]), "+f"(c[1]), "+f"(c[2]), "+f"(c[3])
        : "r"(a[0]), "r"(a[1]), "r"(a[2]), "r"(a[3]), "r"(b0), "r"(b1));
}
__device__ __forceinline__ void ldsm4(unsigned &r0, unsigned &r1, unsigned &r2,
                                      unsigned &r3, unsigned addr) {
    asm volatile("ldmatrix.sync.aligned.m8n8.x4.shared.b16 {%0,%1,%2,%3}, [%4];"
                 : "=r"(r0), "=r"(r1), "=r"(r2), "=r"(r3) : "r"(addr));
}
__device__ __forceinline__ void ldsm4t(unsigned &r0, unsigned &r1, unsigned &r2,
                                       unsigned &r3, unsigned addr) {
    asm volatile("ldmatrix.sync.aligned.m8n8.x4.trans.shared.b16 {%0,%1,%2,%3}, [%4];"
                 : "=r"(r0), "=r"(r1), "=r"(r2), "=r"(r3) : "r"(addr));
}
__device__ __forceinline__ void cp16(unsigned d, const void* s) {
    asm volatile("cp.async.cg.shared.global [%0], [%1], 16;" :: "r"(d), "l"(s));
}
__device__ __forceinline__ void cp16z(unsigned d, const void* s, int ssz) {
    asm volatile("cp.async.cg.shared.global [%0], [%1], 16, %2;"
                 :: "r"(d), "l"(s), "r"(ssz));
}
__device__ __forceinline__ void cp_commit() {
    asm volatile("cp.async.commit_group;");
}
template <int N>
__device__ __forceinline__ void cp_wait() {
    asm volatile("cp.async.wait_group %0;" :: "n"(N));
}
__device__ __forceinline__ void store2(float* C, size_t idx, float v0, float v1) {
    *(float2*)&C[idx] = make_float2(v0, v1);
}
__device__ __forceinline__ void store2(__half* C, size_t idx, float v0, float v1) {
    *(unsigned*)&C[idx] = pack2h(v0, v1);
}

// ---------------------------------------------------------------------------
// Single merged fp32 -> fp16 convert for all 5 tensors (uint4 stores).
// ---------------------------------------------------------------------------
#define CVT_N4 8765440
__global__ void cvt_all(const float4* __restrict__ x,  const float4* __restrict__ wq,
                        const float4* __restrict__ wo, const float4* __restrict__ k,
                        const float4* __restrict__ v,
                        uint2* xh, uint2* wqh, uint2* woh, uint2* kh, uint2* vh)
{
    int i = (blockIdx.x * blockDim.x + threadIdx.x) * 2;
    const float4* s; uint2* d; int o;
    if (i < 2097152)      { s = x;  d = xh;  o = i; }
    else if (i < 2359296) { s = wq; d = wqh; o = i - 2097152; }
    else if (i < 2621440) { s = wo; d = woh; o = i - 2359296; }
    else if (i < 5693440) { s = k;  d = kh;  o = i - 2621440; }
    else if (i < 8765440) { s = v;  d = vh;  o = i - 5693440; }
    else return;
    uint2 a = cvt4(s[o]);
    uint2 b = cvt4(s[o + 1]);
    uint4 w; w.x = a.x; w.y = a.y; w.z = b.x; w.w = b.y;
    *(uint4*)&d[o] = w;
}

// ---------------------------------------------------------------------------
// C[m,n] = (sum_k A[m,k]*W[n,k] + bias[n]) * alpha — fp16 m16n8k16, cp.async.
// 128x128 tile, BK=64, 3-stage pipeline, 1 barrier/iter (16 iters).
// 256 threads = 8 warps (2M x 4N), warp tile 64x32 (R13 layout).
// Row stride 72 halves (144B): ldsm rows land on distinct 16B slots mod 128B.
// ---------------------------------------------------------------------------
#define GSTR   72
#define G_HALF (128 * GSTR)               // halves per (A or W) stage
#define G_STGB (2 * G_HALF * 2)           // bytes per stage = 36864
#define G_SMEM (3 * G_STGB)               // 110592

template <typename OutT>
__global__ __launch_bounds__(256, 2)
void gemm_h(const __half* __restrict__ A, const __half* __restrict__ W,
            const float* __restrict__ bias, OutT* __restrict__ C,
            int M, int N, int K, float alpha)
{
    extern __shared__ __align__(16) char dynsm[];
    const unsigned base = (unsigned)__cvta_generic_to_shared(dynsm);

    const int tid  = threadIdx.x;
    const int lane = tid & 31;
    const int wid  = tid >> 5;
    const int g    = lane >> 2;
    const int t    = lane & 3;
    const int wm   = (wid & 1) * 64;
    const int wn   = (wid >> 1) * 32;
    const int m0   = blockIdx.y * 128;
    const int n0   = blockIdx.x * 128;

    // loader: row r (0..127), 4 chunks of 16B per matrix (64 halves/row)
    const int r  = tid >> 1;
    const int c0 = (tid & 1) * 32;   // halves 0 or 32 (2x16B each side)

    const __half* Ap = A + (size_t)(m0 + r) * K + c0;
    const __half* Wp = W + (size_t)(n0 + r) * K + c0;
    const unsigned sOff = (unsigned)((r * GSTR + c0) * 2);

    auto cpstage = [&](int stage) {
        int k0 = stage * 64;
        unsigned sb = base + (unsigned)(stage % 3) * G_STGB;
        unsigned ab = sb + sOff;
        unsigned wb = sb + G_HALF * 2 + sOff;
        cp16(ab,      Ap + k0);
        cp16(ab + 16, Ap + k0 + 8);
        cp16(ab + 32, Ap + k0 + 16);
        cp16(ab + 48, Ap + k0 + 24);
        cp16(wb,      Wp + k0);
        cp16(wb + 16, Wp + k0 + 8);
        cp16(wb + 32, Wp + k0 + 16);
        cp16(wb + 48, Wp + k0 + 24);
        cp_commit();
    };

    const int ro = lane & 7;
    const int ti = lane >> 3;
    const unsigned aLane = (unsigned)(((wm + (ti & 1) * 8 + ro) * GSTR + (ti >> 1) * 8) * 2);
    const unsigned bLane = (unsigned)(((wn + (ti >> 1) * 8 + ro) * GSTR + (ti & 1) * 8) * 2);

    float acc[4][4][4];
#pragma unroll
    for (int i = 0; i < 4; i++)
#pragma unroll
        for (int j = 0; j < 4; j++)
#pragma unroll
            for (int e = 0; e < 4; e++) acc[i][j][e] = 0.f;

    const int NITER = K / 64;   // 16
    cpstage(0);
    cpstage(1);

    for (int i = 0; i < NITER; i++) {
        if (i + 1 < NITER) cp_wait<1>(); else cp_wait<0>();
        __syncthreads();
        if (i + 2 < NITER) cpstage(i + 2);

        const unsigned sb = base + (unsigned)(i % 3) * G_STGB;
        const unsigned aB = sb;
        const unsigned wB = sb + G_HALF * 2;
#pragma unroll
        for (int ks = 0; ks < 4; ks++) {
            unsigned af[4][4], bf[4][2];
#pragma unroll
            for (int mi = 0; mi < 4; mi++)
                ldsm4(af[mi][0], af[mi][1], af[mi][2], af[mi][3],
                      aB + aLane + (unsigned)((mi * 16 * GSTR + ks * 16) * 2));
#pragma unroll
            for (int np = 0; np < 2; np++)
                ldsm4(bf[2 * np][0], bf[2 * np][1], bf[2 * np + 1][0], bf[2 * np + 1][1],
                      wB + bLane + (unsigned)((np * 16 * GSTR + ks * 16) * 2));
#pragma unroll
            for (int mi = 0; mi < 4; mi++)
#pragma unroll
                for (int ni = 0; ni < 4; ni++)
                    mma_f16(acc[mi][ni], af[mi], bf[ni][0], bf[ni][1]);
        }
    }

#pragma unroll
    for (int mi = 0; mi < 4; mi++) {
#pragma unroll
        for (int ni = 0; ni < 4; ni++) {
            int mA = m0 + wm + mi * 16 + g;
            int nA = n0 + wn + ni * 8 + 2 * t;
            float b0 = bias[nA], b1 = bias[nA + 1];
            store2(C, (size_t)mA * N + nA,
                   (acc[mi][ni][0] + b0) * alpha, (acc[mi][ni][1] + b1) * alpha);
            store2(C, (size_t)(mA + 8) * N + nA,
                   (acc[mi][ni][2] + b0) * alpha, (acc[mi][ni][3] + b1) * alpha);
        }
    }
}

// ---------------------------------------------------------------------------
// Flash attention (unchanged from R13): fp16 mma, 3-stage cp.async, lazy
// softmax (frozen chunk-0 reference), l via ones-column MMA.
// ---------------------------------------------------------------------------
#define CH     64
#define KSTR   72
#define NCH    ((SK + CH - 1) / CH)
#define A_HALF (CH * KSTR)
#define A_STGB (2 * A_HALF * 2)
#define A_SMEM (3 * A_STGB)

__global__ __launch_bounds__(256, 2)
void attn_h(const __half* __restrict__ Kin, const __half* __restrict__ Vin,
            __half* __restrict__ Out)
{
    extern __shared__ __align__(16) char dynsm[];
    const unsigned base = (unsigned)__cvta_generic_to_shared(dynsm);

    const int tid  = threadIdx.x;
    const int lane = tid & 31;
    const int wid  = tid >> 5;
    const int g    = lane >> 2;
    const int t    = lane & 3;
    const int b    = blockIdx.z;
    const int h    = blockIdx.y;

    const int key = tid >> 2;
    const int d0  = (tid & 3) * 16;

    const __half* Kb = Kin + (size_t)b * SK * DM + h * DH;
    const __half* Vb = Vin + (size_t)b * SK * DM + h * DH;
    const unsigned sOff = (unsigned)((key * KSTR + d0) * 2);

    auto cpstage = [&](int ci) {
        int s = ci * CH + key;
        int ssz = (s < SK) ? 16 : 0;
        size_t go = (size_t)(s < SK ? s : 0) * DM + d0;
        unsigned sb = base + (unsigned)(ci % 3) * A_STGB;
        unsigned kb = sb + sOff;
        unsigned vb = sb + A_HALF * 2 + sOff;
        cp16z(kb,      Kb + go,     ssz);
        cp16z(kb + 16, Kb + go + 8, ssz);
        cp16z(vb,      Vb + go,     ssz);
        cp16z(vb + 16, Vb + go + 8, ssz);
        cp_commit();
    };

    // Q fragments (fp16, pre-scaled by SCALE)
    const int rb = b * TQ + blockIdx.x * 128 + wid * 16;
    unsigned qf[4][4];
#pragma unroll
    for (int kt = 0; kt < 4; kt++) {
        int col = h * DH + kt * 16 + 2 * t;
        qf[kt][0] = *(const unsigned*)&g_qh[(size_t)(rb + g)     * DM + col];
        qf[kt][1] = *(const unsigned*)&g_qh[(size_t)(rb + g + 8) * DM + col];
        qf[kt][2] = *(const unsigned*)&g_qh[(size_t)(rb + g)     * DM + col + 8];
        qf[kt][3] = *(const unsigned*)&g_qh[(size_t)(rb + g + 8) * DM + col + 8];
    }

    const int ro = lane & 7;
    const int ti = lane >> 3;
    const unsigned kLane = (unsigned)((((ti >> 1) * 8 + ro) * KSTR + (ti & 1) * 8) * 2);
    const unsigned vLane = (unsigned)((((ti & 1) * 8 + ro) * KSTR + (ti >> 1) * 8) * 2);

    float nb0 = 0.f, nb1 = 0.f;
    float lacc[4] = {0.f, 0.f, 0.f, 0.f};
    float o[8][4];
#pragma unroll
    for (int nt = 0; nt < 8; nt++)
#pragma unroll
        for (int e = 0; e < 4; e++) o[nt][e] = 0.f;

    const unsigned ones2 = 0x3C003C00u;

    cpstage(0);
    cpstage(1);

    for (int i = 0; i < NCH; i++) {
        if (i + 1 < NCH) cp_wait<1>(); else cp_wait<0>();
        __syncthreads();
        if (i + 2 < NCH) cpstage(i + 2);

        const unsigned sb = base + (unsigned)(i % 3) * A_STGB;

        // ---- S = Q · K^T ----
        float sacc[8][4];
#pragma unroll
        for (int nt = 0; nt < 8; nt++)
#pragma unroll
            for (int e = 0; e < 4; e++) sacc[nt][e] = 0.f;

        const unsigned kB = sb + kLane;
#pragma unroll
        for (int kt = 0; kt < 4; kt++) {
#pragma unroll
            for (int np = 0; np < 4; np++) {
                unsigned b0e, b1e, b0o, b1o;
                ldsm4(b0e, b1e, b0o, b1o,
                      kB + (unsigned)((np * 16 * KSTR + kt * 16) * 2));
                mma_f16(sacc[2 * np],     qf[kt], b0e, b1e);
                mma_f16(sacc[2 * np + 1], qf[kt], b0o, b1o);
            }
        }

        // ---- tail mask ----
        const int s0c = i * CH;
        if (s0c + CH > SK) {
#pragma unroll
            for (int nt = 0; nt < 8; nt++) {
                int c = s0c + nt * 8 + 2 * t;
                if (c >= SK)     { sacc[nt][0] = -INFINITY; sacc[nt][2] = -INFINITY; }
                if (c + 1 >= SK) { sacc[nt][1] = -INFINITY; sacc[nt][3] = -INFINITY; }
            }
        }

        // ---- chunk 0: freeze softmax reference ----
        if (i == 0) {
            float mx0 = -INFINITY, mx1 = -INFINITY;
#pragma unroll
            for (int nt = 0; nt < 8; nt++) {
                mx0 = fmaxf(mx0, fmaxf(sacc[nt][0], sacc[nt][1]));
                mx1 = fmaxf(mx1, fmaxf(sacc[nt][2], sacc[nt][3]));
            }
            mx0 = fmaxf(mx0, __shfl_xor_sync(0xffffffffu, mx0, 1));
            mx0 = fmaxf(mx0, __shfl_xor_sync(0xffffffffu, mx0, 2));
            mx1 = fmaxf(mx1, __shfl_xor_sync(0xffffffffu, mx1, 1));
            mx1 = fmaxf(mx1, __shfl_xor_sync(0xffffffffu, mx1, 2));
            nb0 = -mx0 * LOG2E;
            nb1 = -mx1 * LOG2E;
        }

        // ---- P = ex2(s*log2e + nb) in fp16x2 ----
        unsigned punt[8][2];
#pragma unroll
        for (int nt = 0; nt < 8; nt++) {
            float a0 = fmaf(sacc[nt][0], LOG2E, nb0);
            float a1 = fmaf(sacc[nt][1], LOG2E, nb0);
            float a2 = fmaf(sacc[nt][2], LOG2E, nb1);
            float a3 = fmaf(sacc[nt][3], LOG2E, nb1);
            punt[nt][0] = ex2h2(pack2h(a0, a1));
            punt[nt][1] = ex2h2(pack2h(a2, a3));
        }

        // ---- O += P · V ; l += P · 1 ----
        const unsigned vB = sb + A_HALF * 2 + vLane;
#pragma unroll
        for (int kt2 = 0; kt2 < 4; kt2++) {
            unsigned pa[4];
            pa[0] = punt[2 * kt2][0];
            pa[1] = punt[2 * kt2][1];
            pa[2] = punt[2 * kt2 + 1][0];
            pa[3] = punt[2 * kt2 + 1][1];
            mma_f16(lacc, pa, ones2, ones2);
#pragma unroll
            for (int np = 0; np < 4; np++) {
                unsigned b0e, b1e, b0o, b1o;
                ldsm4t(b0e, b1e, b0o, b1o,
                       vB + (unsigned)((kt2 * 16 * KSTR + np * 16) * 2));
                mma_f16(o[2 * np],     pa, b0e, b1e);
                mma_f16(o[2 * np + 1], pa, b0o, b1o);
            }
        }
    }

    float inv0 = 1.f / lacc[0];
    float inv1 = 1.f / lacc[2];

#pragma unroll
    for (int nt = 0; nt < 8; nt++) {
        int col = h * DH + nt * 8 + 2 * t;
        *(unsigned*)&Out[(size_t)(rb + g) * DM + col] =
            pack2h(o[nt][0] * inv0, o[nt][1] * inv0);
        *(unsigned*)&Out[(size_t)(rb + g + 8) * DM + col] =
            pack2h(o[nt][2] * inv1, o[nt][3] * inv1);
    }
}

// ---------------------------------------------------------------------------
extern "C" void kernel_launch(void* const* d_in, const int* in_sizes, int n_in,
                              void* d_out, int out_size)
{
    const float* x  = (const float*)d_in[0];
    const float* k  = (const float*)d_in[1];
    const float* v  = (const float*)d_in[2];
    const float* wq = (const float*)d_in[3];
    const float* bq = (const float*)d_in[4];
    const float* wo = (const float*)d_in[5];
    const float* bo = (const float*)d_in[6];
    float* out = (float*)d_out;

    void *p_xh, *p_wqh, *p_woh, *p_kh, *p_vh, *p_qh, *p_ah;
    cudaGetSymbolAddress(&p_xh, g_xh);
    cudaGetSymbolAddress(&p_wqh, g_wqh);
    cudaGetSymbolAddress(&p_woh, g_woh);
    cudaGetSymbolAddress(&p_kh, g_kh);
    cudaGetSymbolAddress(&p_vh, g_vh);
    cudaGetSymbolAddress(&p_qh, g_qh);
    cudaGetSymbolAddress(&p_ah, g_ah);
    __half* xh  = (__half*)p_xh;
    __half* wqh = (__half*)p_wqh;
    __half* woh = (__half*)p_woh;
    __half* kh  = (__half*)p_kh;
    __half* vh  = (__half*)p_vh;
    __half* qh  = (__half*)p_qh;
    __half* ah  = (__half*)p_ah;

    static int attr_done = 0;
    if (!attr_done) {
        cudaFuncSetAttribute(gemm_h<__half>,
                             cudaFuncAttributeMaxDynamicSharedMemorySize, G_SMEM);
        cudaFuncSetAttribute(gemm_h<float>,
                             cudaFuncAttributeMaxDynamicSharedMemorySize, G_SMEM);
        cudaFuncSetAttribute(attn_h,
                             cudaFuncAttributeMaxDynamicSharedMemorySize, A_SMEM);
        attr_done = 1;
    }

    const int M = BSZ * TQ, N = DM, K = DM;

    // 0) all fp32 -> fp16 converts in one launch
    {
        int nthread = CVT_N4 / 2;
        cvt_all<<<(nthread + 255) / 256, 256>>>(
            (const float4*)x, (const float4*)wq, (const float4*)wo,
            (const float4*)k, (const float4*)v,
            (uint2*)xh, (uint2*)wqh, (uint2*)woh, (uint2*)kh, (uint2*)vh);
    }
    // 1) Q projection (+bias, *SCALE) -> fp16
    {
        dim3 grid(N / 128, M / 128);
        gemm_h<__half><<<grid, 256, G_SMEM>>>(xh, wqh, bq, qh, M, N, K, SCALE);
    }
    // 2) Attention -> fp16
    {
        dim3 grid(TQ / 128, NH, BSZ);
        attn_h<<<grid, 256, A_SMEM>>>(kh, vh, ah);
    }
    // 3) Output projection (+bias) -> fp32
    {
        dim3 grid(N / 128, M / 128);
        gemm_h<float><<<grid, 256, G_SMEM>>>(ah, woh, bo, out, M, N, K, 1.0f);
    }
}